// round 15
// baseline (speedup 1.0000x reference)
#include <cuda_runtime.h>
#include <math.h>

#define BB 8
#define CC 4
#define HH 512
#define WW 512
#define NPIX (HH*WW)

#define SEG  16         // rows per thread in col pass
#define NSEG 32         // segments per column
#define CPB  16         // columns per block (CPB*NSEG == 512 threads)

// Scratch (device globals; allocation in kernel_launch is forbidden)
static __device__ unsigned int d_gp[BB*NPIX];   // packed col g: pol0 lo16, pol1 hi16 (8 MB)
static __device__ int          d_minmax[BB*4];  // per b: pmin2,pmax2,nmin2,nmax2 (float bits)
static __device__ double       d_S[BB*3*4];     // per b: {S_pos,S_neg,S_one} x 4 slices
static __device__ int          d_count;         // zero-init; self-reset by row last block

// ---------------------------------------------------------------------------
// Column pass (256 blocks of 512 for full-SM balance).
// g[i] = min(i + prefmin(m[j]-j), -i + sufmin(m[j]+j)); both polarities packed
// in one u32 halfword pair via vmins2/vadd2/vsub2 (ranges within signed-16).
// ---------------------------------------------------------------------------
__global__ void __launch_bounds__(CPB*NSEG) col_kernel(const float* __restrict__ yt) {
    if (blockIdx.x == 0) {
        int t = threadIdx.x;
        if (t < BB*4) d_minmax[t] = (t & 1) ? 0 : 0x7F800000;
        if (t >= 64 && t < 64 + BB*3*4) d_S[t - 64] = 0.0;
    }

    __shared__ unsigned sA[NSEG][CPB], sB[NSEG][CPB];

    int b    = blockIdx.x >> 5;                 // 32 col-tiles per batch
    int c    = threadIdx.x & (CPB-1);
    int col  = ((blockIdx.x & 31) * CPB) + c;
    int seg  = threadIdx.x / CPB;
    int r0   = seg * SEG;

    const float* src = yt + ((size_t)(b*CC + 1) << 18) + col;

    unsigned mb = 0;
    unsigned PA = 0x40004000u, PB = 0x40004000u;   // 16384 per half
    #pragma unroll
    for (int j = 0; j < SEG; j++) {
        int r = r0 + j;
        float v = __ldg(src + (size_t)r * WW);
        int ism = (v != 0.0f);
        mb |= (unsigned)ism << j;
        unsigned pm = ism ? 0x00000400u : 0x04000000u;  // (m0 lo, m1 hi)
        unsigned rr = (unsigned)r | ((unsigned)r << 16);
        PA = __vmins2(PA, __vsub2(pm, rr));
        PB = __vmins2(PB, __vadd2(pm, rr));
    }
    sA[seg][c] = PA; sB[seg][c] = PB;
    __syncthreads();

    unsigned cA = 0x40004000u, cB = 0x40004000u;
    for (int s = 0; s < seg; s++)      cA = __vmins2(cA, sA[s][c]);
    for (int s = seg+1; s < NSEG; s++) cB = __vmins2(cB, sB[s][c]);

    unsigned freg[SEG];
    unsigned rA = cA;
    #pragma unroll
    for (int j = 0; j < SEG; j++) {
        int r = r0 + j;
        unsigned pm = ((mb >> j) & 1) ? 0x00000400u : 0x04000000u;
        unsigned rr = (unsigned)r | ((unsigned)r << 16);
        rA = __vmins2(rA, __vsub2(pm, rr));
        freg[j] = __vadd2(rA, rr);
    }

    unsigned* gp = d_gp + (size_t)b * NPIX + col;
    unsigned rB = cB;
    #pragma unroll
    for (int j = SEG-1; j >= 0; j--) {
        int r = r0 + j;
        unsigned pm = ((mb >> j) & 1) ? 0x00000400u : 0x04000000u;
        unsigned rr = (unsigned)r | ((unsigned)r << 16);
        rB = __vmins2(rB, __vadd2(pm, rr));
        gp[(size_t)r * WW] = __vmins2(freg[j], __vsub2(rB, rr));
    }
}

// ---------------------------------------------------------------------------
// Row pass + accumulation + finalize. 256 threads/block, each thread owns two
// ADJACENT pixels (2j, 2j+1): LDG.64 loads, halved reduction cost per pixel.
// Exact pruned parabola min (candidates at radius r are >= r^2). Boundary
// <=> pos^2 == 1. Last block applies normalization and writes the scalar.
// ---------------------------------------------------------------------------
__device__ __forceinline__ float sigf(float x) {
    return __fdividef(1.0f, 1.0f + __expf(-x));
}

__global__ void __launch_bounds__(256) row_kernel(const float* __restrict__ yp,
                                                  float* __restrict__ out) {
    __shared__ float2 s[WW];
    __shared__ float red[7][8];
    int b   = blockIdx.x >> 9;
    int row = blockIdx.x & 511;
    int j   = threadIdx.x;          // 0..255
    int pA  = 2*j, pB = 2*j + 1;
    size_t base = (size_t)b * NPIX + (size_t)row * WW;

    uint2 gg = *(const uint2*)(d_gp + base + pA);   // 8B aligned (pA even)
    int gA0 = (int)(gg.x & 0xFFFFu), gA1 = (int)(gg.x >> 16);
    int gB0 = (int)(gg.y & 0xFFFFu), gB1 = (int)(gg.y >> 16);
    float aA0 = (float)(gA0*gA0), aA1 = (float)(gA1*gA1);
    float aB0 = (float)(gB0*gB0), aB1 = (float)(gB1*gB1);
    s[pA] = make_float2(aA0, aA1);
    s[pB] = make_float2(aB0, aB1);
    __syncthreads();

    float bA0 = aA0, bA1 = aA1, bB0 = aB0, bB1 = aB1;
    for (int r = 1; r < WW; r++) {
        float r2 = (float)(r * r);
        if (r2 >= fmaxf(fmaxf(bA0, bA1), fmaxf(bB0, bB1))) break;
        int lA = pA - r, lB = pB - r, rA = pA + r, rB = pB + r;
        if (lA >= 0) { float2 v = s[lA]; bA0 = fminf(bA0, v.x + r2); bA1 = fminf(bA1, v.y + r2); }
        if (lB >= 0) { float2 v = s[lB]; bB0 = fminf(bB0, v.x + r2); bB1 = fminf(bB1, v.y + r2); }
        if (rA < WW) { float2 v = s[rA]; bA0 = fminf(bA0, v.x + r2); bA1 = fminf(bA1, v.y + r2); }
        if (rB < WW) { float2 v = s[rB]; bB0 = fminf(bB0, v.x + r2); bB1 = fminf(bB1, v.y + r2); }
    }

    // Per-pixel contributions (exclude boundary pixels: pos^2 == 1).
    float posA = sqrtf(bA0), negA = sqrtf(bA1);
    float posB = sqrtf(bB0), negB = sqrtf(bB1);
    const float* pbase = yp + ((size_t)(b*CC) << 18) + (size_t)row * WW + pA;
    float sA_ = 0.f, sB_ = 0.f;
    #pragma unroll
    for (int ch = 0; ch < CC; ch++) {
        float2 y = *(const float2*)(pbase + (size_t)ch * NPIX);
        sA_ += sigf(y.x);
        sB_ += sigf(y.y);
    }
    bool nbA = (bA0 != 1.0f), nbB = (bB0 != 1.0f);
    float t1 = (nbA ? sA_ * posA : 0.0f) + (nbB ? sB_ * posB : 0.0f);
    float t2 = (nbA ? sA_ * negA : 0.0f) + (nbB ? sB_ * negB : 0.0f);
    float t3 = (nbA ? sA_        : 0.0f) + (nbB ? sB_        : 0.0f);

    // Block reduction of 7 values: min0,max0,min1,max1,t1,t2,t3
    float v0 = fminf(bA0, bB0), v1 = fmaxf(bA0, bB0);
    float v2 = fminf(bA1, bB1), v3 = fmaxf(bA1, bB1);
    #pragma unroll
    for (int o = 16; o; o >>= 1) {
        v0 = fminf(v0, __shfl_xor_sync(0xffffffffu, v0, o));
        v1 = fmaxf(v1, __shfl_xor_sync(0xffffffffu, v1, o));
        v2 = fminf(v2, __shfl_xor_sync(0xffffffffu, v2, o));
        v3 = fmaxf(v3, __shfl_xor_sync(0xffffffffu, v3, o));
        t1 += __shfl_xor_sync(0xffffffffu, t1, o);
        t2 += __shfl_xor_sync(0xffffffffu, t2, o);
        t3 += __shfl_xor_sync(0xffffffffu, t3, o);
    }
    int lane = j & 31, w = j >> 5;   // 8 warps
    if (lane == 0) {
        red[0][w] = v0; red[1][w] = v1; red[2][w] = v2; red[3][w] = v3;
        red[4][w] = t1; red[5][w] = t2; red[6][w] = t3;
    }
    __syncthreads();
    if (j < 32) {
        bool act = (j < 8);
        v0 = act ? red[0][j] : __int_as_float(0x7F800000);
        v1 = act ? red[1][j] : 0.0f;
        v2 = act ? red[2][j] : __int_as_float(0x7F800000);
        v3 = act ? red[3][j] : 0.0f;
        t1 = act ? red[4][j] : 0.0f;
        t2 = act ? red[5][j] : 0.0f;
        t3 = act ? red[6][j] : 0.0f;
        #pragma unroll
        for (int o = 4; o; o >>= 1) {
            v0 = fminf(v0, __shfl_xor_sync(0xffffffffu, v0, o));
            v1 = fmaxf(v1, __shfl_xor_sync(0xffffffffu, v1, o));
            v2 = fminf(v2, __shfl_xor_sync(0xffffffffu, v2, o));
            v3 = fmaxf(v3, __shfl_xor_sync(0xffffffffu, v3, o));
            t1 += __shfl_xor_sync(0xffffffffu, t1, o);
            t2 += __shfl_xor_sync(0xffffffffu, t2, o);
            t3 += __shfl_xor_sync(0xffffffffu, t3, o);
        }
        if (j == 0) {
            int sl = blockIdx.x & 3;
            atomicMin(&d_minmax[b*4 + 0], __float_as_int(v0));
            atomicMax(&d_minmax[b*4 + 1], __float_as_int(v1));
            atomicMin(&d_minmax[b*4 + 2], __float_as_int(v2));
            atomicMax(&d_minmax[b*4 + 3], __float_as_int(v3));
            atomicAdd(&d_S[(b*3 + 0)*4 + sl], (double)t1);
            atomicAdd(&d_S[(b*3 + 1)*4 + sl], (double)t2);
            atomicAdd(&d_S[(b*3 + 2)*4 + sl], (double)t3);

            // Finalize in the last-arriving block (atomics above are L2-
            // visible after threadfence; read back via volatile -> L2).
            __threadfence();
            if (atomicAdd(&d_count, 1) == (int)gridDim.x - 1) {
                volatile int*    mm = d_minmax;
                volatile double* SS = d_S;
                double tb = 0.0;
                for (int bi = 0; bi < BB; bi++) {
                    float pmax2 = __int_as_float(mm[bi*4 + 1]);
                    if (pmax2 > 0.0f) {     // mask nonempty
                        float pmin = sqrtf(__int_as_float(mm[bi*4 + 0]));
                        float pmax = sqrtf(pmax2);
                        float nmin = sqrtf(__int_as_float(mm[bi*4 + 2]));
                        float nmax = sqrtf(__int_as_float(mm[bi*4 + 3]));
                        float pr = 1.0f / (pmax - pmin);
                        float nr = 1.0f / (nmax - nmin);
                        float cst = pmin * pr - nmin * nr;
                        double S1 = 0.0, S2 = 0.0, S3 = 0.0;
                        #pragma unroll
                        for (int sl2 = 0; sl2 < 4; sl2++) {
                            S1 += SS[(bi*3 + 0)*4 + sl2];
                            S2 += SS[(bi*3 + 1)*4 + sl2];
                            S3 += SS[(bi*3 + 2)*4 + sl2];
                        }
                        tb += (double)nr * S2 - (double)pr * S1 + (double)cst * S3;
                    }
                }
                out[0] = (float)(tb / (double)((size_t)BB * CC * NPIX));
                d_count = 0;    // self-reset for graph replay
            }
        }
    }
}

extern "C" void kernel_launch(void* const* d_in, const int* in_sizes, int n_in,
                              void* d_out, int out_size) {
    const float* yp = (const float*)d_in[0];  // y_pred (8,4,512,512)
    const float* yt = (const float*)d_in[1];  // y_true (8,4,512,512)
    (void)in_sizes; (void)n_in; (void)out_size;

    col_kernel<<<BB*32, CPB*NSEG>>>(yt);
    row_kernel<<<BB*HH, 256>>>(yp, (float*)d_out);
}